// round 17
// baseline (speedup 1.0000x reference)
#include <cuda_runtime.h>

// ---------------------------------------------------------------------------
// Sparse 3D submanifold U-block, fp32, gather-GEMM-scatter with FFMA2 (f32x2),
// BN+ReLU fused into the gather. Scratch: static device pool. Stream 0 only.
// (Sixteenth submission of the unmeasured FFMA2 kernel — rounds 2-16 all
//  died to broker GPUAcquisitionTimeout. Held byte-identical: the first
//  successful bench must cleanly measure FFMA2 vs. the R1 scalar baseline.)
// ---------------------------------------------------------------------------

#define MAXN 48128  // n0 = 4*12000 = 48000; small slack

__device__ float g_pool[8][(size_t)MAXN * 64];

static inline int ceil_div(int a, int b) { return (a + b - 1) / b; }

__device__ __forceinline__ unsigned long long ffma2(unsigned long long a,
                                                    unsigned long long b,
                                                    unsigned long long c) {
    unsigned long long d;
    asm("fma.rn.f32x2 %0, %1, %2, %3;" : "=l"(d) : "l"(a), "l"(b), "l"(c));
    return d;
}

// ---------------------------------------------------------------------------
// Concat [a | b] along channels (32 + 32 -> 64)
// ---------------------------------------------------------------------------
__global__ void concat_kernel(const float* __restrict__ a,
                              const float* __restrict__ b,
                              float* __restrict__ y, int n0) {
    int idx = blockIdx.x * blockDim.x + threadIdx.x;
    if (idx >= n0 * 64) return;
    int i = idx >> 6, c = idx & 63;
    y[idx] = (c < 32) ? a[i * 32 + c] : b[i * 32 + (c - 32)];
}

// ---------------------------------------------------------------------------
// Dense shortcut GEMM: y[n0,32] = x[n0,64] @ W[64,32]
// ---------------------------------------------------------------------------
__global__ void linear64to32_kernel(const float* __restrict__ x,
                                    const float* __restrict__ W,
                                    float* __restrict__ y, int n0) {
    int idx = blockIdx.x * blockDim.x + threadIdx.x;
    if (idx >= n0 * 32) return;
    int i = idx >> 5, d = idx & 31;
    const float* xr = x + (size_t)i * 64;
    float acc = 0.f;
#pragma unroll
    for (int c = 0; c < 64; c++) acc = fmaf(xr[c], W[c * 32 + d], acc);
    y[idx] = acc;
}

// ---------------------------------------------------------------------------
// Scatter sparse conv with fused BN+ReLU on the input:
//   out[pout[k,p]] += relu(bn(x[pin[k,p]])) @ W[k]     (atomicAdd scatter)
// - pads (pin == nin) are a suffix of each k-list -> whole-tile early exit
// - gathered tile stored row-pair interleaved: sG2[rp][c] = {row2rp_c, row2rp+1_c}
// - weights duplicated (w,w) in SMEM, d-major, even-padded rows -> aligned
//   ulonglong2 loads for the packed FFMA2 micro-GEMM.
// ---------------------------------------------------------------------------
template <int CIN, int COUT>
__global__ void conv_scatter(const float* __restrict__ x,
                             const float* __restrict__ bnp,
                             const float* __restrict__ W,
                             const int* __restrict__ pin,
                             const int* __restrict__ pout,
                             int P, int nin,
                             float* __restrict__ out) {
    constexpr int TP   = 128;
    constexpr int NT   = (COUT >= 64) ? 512 : 256;
    constexpr int DT   = COUT / 16;          // cols per thread: 2 or 4
    constexpr int RPT  = (TP * 16) / NT;     // rows per thread: 8 or 4
    constexpr int NRPT = RPT / 2;            // row-pairs per thread
    constexpr int CINP = CIN + 2;            // even pad (float2 units)
    constexpr int NRP  = TP / 2;

    const int k = blockIdx.y;
    const int base = blockIdx.x * TP;
    const int tid = threadIdx.x;

    const int* pinK = pin + (size_t)k * P;
    const int* poutK = pout + (size_t)k * P;

    // pads are a suffix of each k-list: first pad => whole tile is pads.
    if (pinK[base] == nin) return;

    extern __shared__ char smraw[];
    float2* sG2 = (float2*)smraw;            // [NRP][CINP]
    float2* sW2 = sG2 + NRP * CINP;          // [COUT][CINP]  (d-major, dup'd)
    float*  sS  = (float*)(sW2 + COUT * CINP);
    float*  sT  = sS + CIN;
    int*    sIn = (int*)(sT + CIN);
    int*    sO  = sIn + TP;

    // BN coefficients: y = max(x*s + t, 0)
    for (int c = tid; c < CIN; c += NT) {
        float g = bnp[c], be = bnp[CIN + c], m = bnp[2 * CIN + c], v = bnp[3 * CIN + c];
        float s = g * rsqrtf(v + 1e-4f);
        sS[c] = s;
        sT[c] = be - m * s;
    }
    // duplicated weights, d-major
    const float* Wk = W + (size_t)k * (CIN * COUT);
    for (int i = tid; i < CIN * COUT; i += NT) {
        int c = i / COUT, d = i - c * COUT;
        float w = Wk[i];
        sW2[d * CINP + c] = make_float2(w, w);
    }
    for (int r = tid; r < TP; r += NT) {
        int p = base + r;
        int idx = (p < P) ? pinK[p] : nin;
        sIn[r] = idx;
        sO[r] = (idx == nin) ? -1 : poutK[p];
    }
    __syncthreads();

    // gather + BN + ReLU, row-pair interleaved write
    constexpr int Q = CIN / 4;
    float* sGf = (float*)sG2;
    for (int t = tid; t < TP * Q; t += NT) {
        int r = t / Q, q = t - r * Q;
        int c0 = q * 4;
        int idx = sIn[r];
        float4 v4 = make_float4(0.f, 0.f, 0.f, 0.f);
        if (idx < nin) {
            float4 xv = *(const float4*)(x + (size_t)idx * CIN + c0);
            v4.x = fmaxf(fmaf(xv.x, sS[c0 + 0], sT[c0 + 0]), 0.f);
            v4.y = fmaxf(fmaf(xv.y, sS[c0 + 1], sT[c0 + 1]), 0.f);
            v4.z = fmaxf(fmaf(xv.z, sS[c0 + 2], sT[c0 + 2]), 0.f);
            v4.w = fmaxf(fmaf(xv.w, sS[c0 + 3], sT[c0 + 3]), 0.f);
        }
        float* dst = sGf + ((size_t)(r >> 1) * CINP + c0) * 2 + (r & 1);
        dst[0] = v4.x; dst[2] = v4.y; dst[4] = v4.z; dst[6] = v4.w;
    }
    __syncthreads();

    const int dg = tid & 15;
    const int rg = tid >> 4;
    const int d0 = dg * DT;
    const int rp0 = rg * NRPT;

    unsigned long long acc[NRPT][DT];
#pragma unroll
    for (int a = 0; a < NRPT; a++)
#pragma unroll
        for (int u = 0; u < DT; u++) acc[a][u] = 0ull;

#pragma unroll 4
    for (int c = 0; c < CIN; c += 2) {
        ulonglong2 wv[DT];
#pragma unroll
        for (int u = 0; u < DT; u++)
            wv[u] = *(const ulonglong2*)(sW2 + (d0 + u) * CINP + c);
        ulonglong2 gv[NRPT];
#pragma unroll
        for (int a = 0; a < NRPT; a++)
            gv[a] = *(const ulonglong2*)(sG2 + (rp0 + a) * CINP + c);
#pragma unroll
        for (int a = 0; a < NRPT; a++)
#pragma unroll
            for (int u = 0; u < DT; u++) {
                acc[a][u] = ffma2(gv[a].x, wv[u].x, acc[a][u]);
                acc[a][u] = ffma2(gv[a].y, wv[u].y, acc[a][u]);
            }
    }

#pragma unroll
    for (int a = 0; a < NRPT; a++) {
        int r = (rp0 + a) * 2;
        int o0 = sO[r], o1 = sO[r + 1];
#pragma unroll
        for (int u = 0; u < DT; u++) {
            float2 f = *(float2*)&acc[a][u];
            if (o0 >= 0) atomicAdd(out + (size_t)o0 * COUT + d0 + u, f.x);
            if (o1 >= 0) atomicAdd(out + (size_t)o1 * COUT + d0 + u, f.y);
        }
    }
}

// dynamic smem bytes for conv_scatter<CIN,COUT>
static inline int conv_smem(int CIN, int COUT) {
    int CINP = CIN + 2;
    return 64 * CINP * 8 + COUT * CINP * 8 + 2 * CIN * 4 + 128 * 8;
}
static inline int conv_threads(int COUT) { return (COUT >= 64) ? 512 : 256; }

extern "C" void kernel_launch(void* const* d_in, const int* in_sizes, int n_in,
                              void* d_out, int out_size) {
    const float* feats   = (const float*)d_in[0];
    const float* res0_W  = (const float*)d_in[1];
    const float* res0_bn = (const float*)d_in[2];
    const float* down_bn = (const float*)d_in[3];
    const float* down_W  = (const float*)d_in[4];
    const float* res1_W  = (const float*)d_in[5];
    const float* res1_bn = (const float*)d_in[6];
    const float* up_bn   = (const float*)d_in[7];
    const float* up_W    = (const float*)d_in[8];
    const float* t0_bn1  = (const float*)d_in[9];
    const float* t0_W1   = (const float*)d_in[10];
    const float* t0_bn2  = (const float*)d_in[11];
    const float* t0_W2   = (const float*)d_in[12];
    const float* t0_Wsc  = (const float*)d_in[13];
    const float* t1_W    = (const float*)d_in[14];
    const float* t1_bn   = (const float*)d_in[15];
    const int* s0i = (const int*)d_in[16];
    const int* s0o = (const int*)d_in[17];
    const int* s1i = (const int*)d_in[18];
    const int* s1o = (const int*)d_in[19];
    const int* dni = (const int*)d_in[20];
    const int* dno = (const int*)d_in[21];

    const int n0 = in_sizes[0] / 32;
    const int P0 = in_sizes[16] / 27;
    const int P1 = in_sizes[18] / 27;
    const int Pd = in_sizes[20] / 8;
    // center offset pairs every point with itself -> padded subm1 width == n1
    const int n1 = P1;

    float* pool = nullptr;
    cudaGetSymbolAddress((void**)&pool, g_pool);
    const size_t slot = (size_t)MAXN * 64;
    float* S0 = pool + 0 * slot;
    float* S2 = pool + 2 * slot;
    float* S3 = pool + 3 * slot;
    float* S4 = pool + 4 * slot;
    float* S5 = pool + 5 * slot;
    float* S6 = pool + 6 * slot;
    float* S7 = pool + 7 * slot;

    cudaFuncSetAttribute(conv_scatter<32, 32>,
                         cudaFuncAttributeMaxDynamicSharedMemorySize, conv_smem(32, 32));
    cudaFuncSetAttribute(conv_scatter<32, 64>,
                         cudaFuncAttributeMaxDynamicSharedMemorySize, conv_smem(32, 64));
    cudaFuncSetAttribute(conv_scatter<64, 32>,
                         cudaFuncAttributeMaxDynamicSharedMemorySize, conv_smem(64, 32));
    cudaFuncSetAttribute(conv_scatter<64, 64>,
                         cudaFuncAttributeMaxDynamicSharedMemorySize, conv_smem(64, 64));

    dim3 g0(ceil_div(P0, 128), 27);
    dim3 g1(ceil_div(P1, 128), 27);
    dim3 gd(ceil_div(Pd, 128), 8);

    // ---------------- level 0: 2x residual blocks (C32) ----------------
    cudaMemcpyAsync(S0, feats, (size_t)n0 * 32 * 4, cudaMemcpyDeviceToDevice);
    float* X = S0;
    float* O = S3;
    for (int i = 0; i < 2; i++) {
        cudaMemsetAsync(S2, 0, (size_t)n0 * 32 * 4);
        conv_scatter<32, 32><<<g0, conv_threads(32), conv_smem(32, 32)>>>(
            X, res0_bn + (i * 2 + 0) * 128,
            res0_W + (size_t)(i * 2 + 0) * 27 * 1024, s0i, s0o, P0, n0, S2);
        cudaMemcpyAsync(O, X, (size_t)n0 * 32 * 4, cudaMemcpyDeviceToDevice);
        conv_scatter<32, 32><<<g0, conv_threads(32), conv_smem(32, 32)>>>(
            S2, res0_bn + (i * 2 + 1) * 128,
            res0_W + (size_t)(i * 2 + 1) * 27 * 1024, s0i, s0o, P0, n0, O);
        float* t = X; X = O; O = t;
    }
    // X == identity (S0 after two swaps)

    // ---------------- downsample: conv 32->64, K=8 ----------------
    cudaMemsetAsync(S4, 0, (size_t)n1 * 64 * 4);
    conv_scatter<32, 64><<<gd, conv_threads(64), conv_smem(32, 64)>>>(
        X, down_bn, down_W, dni, dno, Pd, n0, S4);

    // ---------------- level 1: 2x residual blocks (C64) ----------------
    float* X1 = S4;
    float* O1 = S7;
    for (int i = 0; i < 2; i++) {
        cudaMemsetAsync(S5, 0, (size_t)n1 * 64 * 4);
        conv_scatter<64, 64><<<g1, conv_threads(64), conv_smem(64, 64)>>>(
            X1, res1_bn + (i * 2 + 0) * 256,
            res1_W + (size_t)(i * 2 + 0) * 27 * 4096, s1i, s1o, P1, n1, S5);
        cudaMemcpyAsync(O1, X1, (size_t)n1 * 64 * 4, cudaMemcpyDeviceToDevice);
        conv_scatter<64, 64><<<g1, conv_threads(64), conv_smem(64, 64)>>>(
            S5, res1_bn + (i * 2 + 1) * 256,
            res1_W + (size_t)(i * 2 + 1) * 27 * 4096, s1i, s1o, P1, n1, O1);
        float* t = X1; X1 = O1; O1 = t;
    }

    // ---------------- upsample (transposed): conv 64->32, K=8 ----------------
    cudaMemsetAsync(S6, 0, (size_t)n0 * 32 * 4);
    conv_scatter<64, 32><<<gd, conv_threads(32), conv_smem(64, 32)>>>(
        X1, up_bn, up_W, dno, dni, Pd, n1, S6);  // swapped in/out lists

    // ---------------- concat + tail0 ----------------
    concat_kernel<<<ceil_div(n0 * 64, 256), 256>>>(X, S6, S5, n0);
    cudaMemsetAsync(S2, 0, (size_t)n0 * 32 * 4);
    conv_scatter<64, 32><<<g0, conv_threads(32), conv_smem(64, 32)>>>(
        S5, t0_bn1, t0_W1, s0i, s0o, P0, n0, S2);
    linear64to32_kernel<<<ceil_div(n0 * 32, 256), 256>>>(S5, t0_Wsc, O, n0);
    conv_scatter<32, 32><<<g0, conv_threads(32), conv_smem(32, 32)>>>(
        S2, t0_bn2, t0_W2, s0i, s0o, P0, n0, O);
    float* XT = O;  // tail0 output

    // ---------------- tail1: residual block (C32) -> d_out ----------------
    cudaMemsetAsync(S2, 0, (size_t)n0 * 32 * 4);
    conv_scatter<32, 32><<<g0, conv_threads(32), conv_smem(32, 32)>>>(
        XT, t1_bn + 0, t1_W + 0, s0i, s0o, P0, n0, S2);
    cudaMemcpyAsync(d_out, XT, (size_t)n0 * 32 * 4, cudaMemcpyDeviceToDevice);
    conv_scatter<32, 32><<<g0, conv_threads(32), conv_smem(32, 32)>>>(
        S2, t1_bn + 128, t1_W + (size_t)27 * 1024, s0i, s0o, P0, n0, (float*)d_out);
}